// round 5
// baseline (speedup 1.0000x reference)
#include <cuda_runtime.h>
#include <cuda_bf16.h>

#define BOLTZMAN 0.001987191f
#define L 64

// Coefficients, written by gle_coef_kernel, read by main kernel after PDL sync.
__device__ __align__(16) float g_cA[L];  // g_cA[s] = -mk[64-s] (s>=1), [0]=0
__device__ __align__(16) float g_cB[L];  // g_cB[s] =  h[64-s]  (s>=1), [0]=0
__device__ float g_sc[2];                // [0] = -mk[0], [1] = h[0]

// Tiny coefficient kernel: 1 block, 64 threads.
__global__ void gle_coef_kernel(const float* __restrict__ h,
                                const int* __restrict__ Traw,
                                const float* __restrict__ mass) {
    __shared__ float hs[L];
    int k = threadIdx.x;
    hs[k] = h[k];
    __syncthreads();

    float mk = 0.0f;
    #pragma unroll 8
    for (int j = 0; j + k < L; ++j) mk += hs[j] * hs[j + k];

    int ti = Traw[0];
    float T = (ti > 0 && ti < 10000000) ? (float)ti : __int_as_float(ti);
    mk *= mass[0] * BOLTZMAN * T;

    if (k == 0) {
        g_sc[0] = -mk;
        g_sc[1] = hs[0];
        g_cA[0] = 0.0f;
        g_cB[0] = 0.0f;
    } else {
        g_cA[L - k] = -mk;
        g_cB[L - k] = hs[k];
    }
}

// Persistent software-pipelined streaming kernel.
// Grid-stride over 64-channel tiles; next tile's loads issued before current
// tile's compute so the memory pipe never drains at tile boundaries.
// 16 lanes per channel, 2 channels per thread per tile.
__global__ void __launch_bounds__(512, 2) gle_main_kernel(
    const float* __restrict__ v,
    const float* __restrict__ vlist,
    const float* __restrict__ wlist,
    const float* __restrict__ wnew,
    float* __restrict__ out,
    int nch) {
    int tid = threadIdx.x;
    int grp = tid >> 4;                  // 0..31
    int q   = tid & 15;                  // float4 index within 64-float row
    int stride = gridDim.x * 64;         // channels per grid sweep
    int base = blockIdx.x * 64;

    const float4* vl4 = (const float4*)vlist;
    const float4* wl4 = (const float4*)wlist;

    // ---- prologue: load first tile ----
    int c0 = base + grp, c1 = c0 + 32;
    int p0 = (c0 < nch ? c0 : 0), p1 = (c1 < nch ? c1 : 0);
    float4 a0 = __ldcs(vl4 + p0 * 16 + q);
    float4 b0 = __ldcs(wl4 + p0 * 16 + q);
    float4 a1 = __ldcs(vl4 + p1 * 16 + q);
    float4 b1 = __ldcs(wl4 + p1 * 16 + q);
    float vv0 = 0.f, wn0 = 0.f, vv1 = 0.f, wn1 = 0.f;
    if (q == 0) {
        vv0 = __ldg(&v[p0]);  wn0 = __ldg(&wnew[p0]);
        vv1 = __ldg(&v[p1]);  wn1 = __ldg(&wnew[p1]);
    }

    // ---- PDL: wait for coef kernel (hidden under the loads above), read coefs once ----
    cudaGridDependencySynchronize();
    const float4 ca = __ldg(&((const float4*)g_cA)[q]);
    const float4 cb = __ldg(&((const float4*)g_cB)[q]);
    const float s0 = __ldg(&g_sc[0]);
    const float s1 = __ldg(&g_sc[1]);

    while (true) {
        // ---- prefetch next tile before touching current tile's data ----
        int nbase = base + stride;
        bool have_next = (nbase < nch);
        float4 na0, nb0, na1, nb1;
        float nvv0 = 0.f, nwn0 = 0.f, nvv1 = 0.f, nwn1 = 0.f;
        int nc0 = nbase + grp, nc1 = nc0 + 32;
        if (have_next) {
            int q0 = (nc0 < nch ? nc0 : 0), q1 = (nc1 < nch ? nc1 : 0);
            na0 = __ldcs(vl4 + q0 * 16 + q);
            nb0 = __ldcs(wl4 + q0 * 16 + q);
            na1 = __ldcs(vl4 + q1 * 16 + q);
            nb1 = __ldcs(wl4 + q1 * 16 + q);
            if (q == 0) {
                nvv0 = __ldg(&v[q0]);  nwn0 = __ldg(&wnew[q0]);
                nvv1 = __ldg(&v[q1]);  nwn1 = __ldg(&wnew[q1]);
            }
        }

        // ---- compute current tile ----
        float acc0 = a0.x * ca.x + a0.y * ca.y + a0.z * ca.z + a0.w * ca.w
                   + b0.x * cb.x + b0.y * cb.y + b0.z * cb.z + b0.w * cb.w;
        float acc1 = a1.x * ca.x + a1.y * ca.y + a1.z * ca.z + a1.w * ca.w
                   + b1.x * cb.x + b1.y * cb.y + b1.z * cb.z + b1.w * cb.w;

        acc0 += __shfl_down_sync(0xffffffffu, acc0, 8, 16);
        acc1 += __shfl_down_sync(0xffffffffu, acc1, 8, 16);
        acc0 += __shfl_down_sync(0xffffffffu, acc0, 4, 16);
        acc1 += __shfl_down_sync(0xffffffffu, acc1, 4, 16);
        acc0 += __shfl_down_sync(0xffffffffu, acc0, 2, 16);
        acc1 += __shfl_down_sync(0xffffffffu, acc1, 2, 16);
        acc0 += __shfl_down_sync(0xffffffffu, acc0, 1, 16);
        acc1 += __shfl_down_sync(0xffffffffu, acc1, 1, 16);

        if (q == 0) {
            if (c0 < nch) __stcs(&out[c0], acc0 + vv0 * s0 + wn0 * s1);
            if (c1 < nch) __stcs(&out[c1], acc1 + vv1 * s0 + wn1 * s1);
        }

        if (!have_next) break;
        a0 = na0; b0 = nb0; a1 = na1; b1 = nb1;
        vv0 = nvv0; wn0 = nwn0; vv1 = nvv1; wn1 = nwn1;
        base = nbase; c0 = nc0; c1 = nc1;
    }
}

extern "C" void kernel_launch(void* const* d_in, const int* in_sizes, int n_in,
                              void* d_out, int out_size) {
    // metadata order: v, T, dt, mass, h, v_list, w_list, w_new
    const float* v     = (const float*)d_in[0];
    const int*   Traw  = (const int*)  d_in[1];
    const float* mass  = (const float*)d_in[3];
    const float* h     = (const float*)d_in[4];
    const float* vlist = (const float*)d_in[5];
    const float* wlist = (const float*)d_in[6];
    const float* wnew  = (const float*)d_in[7];
    float* out = (float*)d_out;

    int nch = in_sizes[0];                 // 3*NATOM channels

    gle_coef_kernel<<<1, 64>>>(h, Traw, mass);

    int tiles = (nch + 63) / 64;
    int blocks = 592;                      // 4 per SM nominal (148 SMs)
    if (blocks > tiles) blocks = tiles;

    cudaLaunchAttribute attrs[1];
    attrs[0].id = cudaLaunchAttributeProgrammaticStreamSerialization;
    attrs[0].val.programmaticStreamSerializationAllowed = 1;

    cudaLaunchConfig_t cfg = {};
    cfg.gridDim = dim3((unsigned)blocks, 1, 1);
    cfg.blockDim = dim3(512, 1, 1);
    cfg.dynamicSmemBytes = 0;
    cfg.stream = 0;
    cfg.attrs = attrs;
    cfg.numAttrs = 1;

    cudaLaunchKernelEx(&cfg, gle_main_kernel, v, vlist, wlist, wnew, out, nch);
}